// round 7
// baseline (speedup 1.0000x reference)
#include <cuda_runtime.h>
#include <cuda_fp16.h>
#include <cstring>

// PositionalSparseLinear: out[b,o] = sum_k x[b, conn[o,k]] * w[o,k]
//   x: [1024,8192] f32   conn: [8192,32] i32   w: [8192,32] f32   out: [1024,8192] f32
//
// Round 7: bank-scheduled gathers.
//  - fp16-staged transposed SMEM batch tile (BT=8 rows per 16B column), as R5.
//  - Prep kernel sorts each output's 32 (idx,w) pairs by SMEM bank-group
//    (idx & 7) and rotates by (o & 31) before storing transposed
//    cwT[t][o]. At runtime, warp lanes at any k-step then access one entry
//    of each sorted rank 0..31 -> bank-groups are near-uniform: expected
//    crossbar phases per LDS.128 drop 7.4 -> ~5.0 (floor is 4).
//    Summation is commutative so values are identical, only FMA order moves.

#define IN_F   8192
#define OUT_F  8192
#define KW     32
#define BATCH  1024
#define BT     8
#define THREADS 1024
#define O_SPLIT 8
#define O_PER_CTA (OUT_F / O_SPLIT)     // 1024 == THREADS
#define SMEM_BYTES (IN_F * BT * (int)sizeof(__half))   // 131072

__device__ unsigned int g_cwT[KW * OUT_F];   // [slot][o] packed (idx<<16)|half(w)

static __device__ __forceinline__ __half2 u32_as_h2(unsigned int u) {
    __half2 h; memcpy(&h, &u, sizeof(h)); return h;
}

// One warp per output o; lane = k. Ballot-based counting sort by bank group,
// then rotate by o so that runtime step t at lane l reads rank (t+l)&31.
__global__ void psl_prep(const int* __restrict__ conn, const float* __restrict__ w)
{
    const int gtid = blockIdx.x * blockDim.x + threadIdx.x;
    const int o    = gtid >> 5;          // warp id == output index
    const int lane = gtid & 31;          // k index

    const int   c  = conn[(size_t)o * KW + lane];
    const float wv = w   [(size_t)o * KW + lane];
    const unsigned short hb = __half_as_ushort(__float2half_rn(wv));
    const unsigned int packed = ((unsigned int)c << 16) | (unsigned int)hb;

    const int g = c & 7;                 // bank-group of xs[c] (16B granule)

    // rank = #entries with smaller group + #ties in lower lanes
    unsigned int rank = 0, my_mask = 0;
    #pragma unroll
    for (int gg = 0; gg < 8; gg++) {
        unsigned int m = __ballot_sync(0xffffffffu, g == gg);
        if (gg < g)  rank += __popc(m);
        if (gg == g) my_mask = m;
    }
    rank += __popc(my_mask & ((1u << lane) - 1u));

    // slot t holds the element of rank (t + o) & 31
    const int slot = (int)((rank - (unsigned int)o) & 31u);
    g_cwT[(size_t)slot * OUT_F + o] = packed;
}

__global__ __launch_bounds__(THREADS, 1)
void psl_main(const float* __restrict__ x, float* __restrict__ out)
{
    extern __shared__ uint4 xs[];   // xs[col] = 8 halves: rows b0..b0+7 of col

    const int tid = threadIdx.x;
    const int b0  = blockIdx.y * BT;

    // ---- Stage: 8 coalesced row-loads per column -> fp16 pack -> STS.128 ----
    const float* xb = x + (size_t)b0 * IN_F;

    #pragma unroll
    for (int c = tid; c < IN_F; c += THREADS) {
        float r0 = xb[c + 0 * (size_t)IN_F];
        float r1 = xb[c + 1 * (size_t)IN_F];
        float r2 = xb[c + 2 * (size_t)IN_F];
        float r3 = xb[c + 3 * (size_t)IN_F];
        float r4 = xb[c + 4 * (size_t)IN_F];
        float r5 = xb[c + 5 * (size_t)IN_F];
        float r6 = xb[c + 6 * (size_t)IN_F];
        float r7 = xb[c + 7 * (size_t)IN_F];

        __half2 h0 = __floats2half2_rn(r0, r1);
        __half2 h1 = __floats2half2_rn(r2, r3);
        __half2 h2 = __floats2half2_rn(r4, r5);
        __half2 h3 = __floats2half2_rn(r6, r7);

        uint4 v;
        memcpy(&v.x, &h0, 4);
        memcpy(&v.y, &h1, 4);
        memcpy(&v.z, &h2, 4);
        memcpy(&v.w, &h3, 4);
        xs[c] = v;
    }
    __syncthreads();

    const int o = blockIdx.x * O_PER_CTA + tid;   // one output per thread
    const unsigned int* __restrict__ cwp = g_cwT + o;

    float a0 = 0.f, a1 = 0.f, a2 = 0.f, a3 = 0.f;
    float a4 = 0.f, a5 = 0.f, a6 = 0.f, a7 = 0.f;

    #pragma unroll 8
    for (int k = 0; k < KW; k++) {
        const unsigned int cw = cwp[(size_t)k * OUT_F];  // coalesced, L2-hot
        const int   c  = (int)(cw >> 16);
        const float wv = __half2float(__ushort_as_half((unsigned short)(cw & 0xffffu)));

        const uint4 hv = xs[c];
        float2 f0 = __half22float2(u32_as_h2(hv.x));
        float2 f1 = __half22float2(u32_as_h2(hv.y));
        float2 f2 = __half22float2(u32_as_h2(hv.z));
        float2 f3 = __half22float2(u32_as_h2(hv.w));
        a0 = fmaf(wv, f0.x, a0);
        a1 = fmaf(wv, f0.y, a1);
        a2 = fmaf(wv, f1.x, a2);
        a3 = fmaf(wv, f1.y, a3);
        a4 = fmaf(wv, f2.x, a4);
        a5 = fmaf(wv, f2.y, a5);
        a6 = fmaf(wv, f3.x, a6);
        a7 = fmaf(wv, f3.y, a7);
    }

    float* op = out + (size_t)b0 * OUT_F + o;
    op[0 * (size_t)OUT_F] = a0;
    op[1 * (size_t)OUT_F] = a1;
    op[2 * (size_t)OUT_F] = a2;
    op[3 * (size_t)OUT_F] = a3;
    op[4 * (size_t)OUT_F] = a4;
    op[5 * (size_t)OUT_F] = a5;
    op[6 * (size_t)OUT_F] = a6;
    op[7 * (size_t)OUT_F] = a7;
}

extern "C" void kernel_launch(void* const* d_in, const int* in_sizes, int n_in,
                              void* d_out, int out_size)
{
    const float* x    = (const float*)d_in[0];   // [1024, 8192] f32
    const int*   conn = (const int*)  d_in[1];   // [8192, 32]   i32
    const float* w    = (const float*)d_in[2];   // [8192, 32]   f32
    float*       out  = (float*)d_out;           // [1024, 8192] f32

    (void)in_sizes; (void)n_in; (void)out_size;

    psl_prep<<<(OUT_F * 32) / 256, 256>>>(conn, w);

    cudaFuncSetAttribute(psl_main,
                         cudaFuncAttributeMaxDynamicSharedMemorySize,
                         SMEM_BYTES);

    dim3 grid(O_SPLIT, BATCH / BT);   // (8, 128) = 1024 CTAs
    psl_main<<<grid, THREADS, SMEM_BYTES>>>(x, out);
}

// round 8
// speedup vs baseline: 1.4103x; 1.4103x over previous
#include <cuda_runtime.h>
#include <cuda_fp16.h>
#include <cstring>

// PositionalSparseLinear: out[b,o] = sum_k x[b, conn[o,k]] * w[o,k]
//   x: [1024,8192] f32   conn: [8192,32] i32   w: [8192,32] f32   out: [1024,8192] f32
//
// Round 8: stride-4 bank-scheduled gathers.
//  R7 showed LDS.128 conflict phases form per 8-lane quarter: consecutive
//  equal bank-groups within a quarter are catastrophic. Fix: store each
//  output's group-sorted entries so runtime step t at lane l reads rank
//  (t + 4*o) & 31 -> within any quarter, ranks are spaced by 4 == one
//  entry per bank-group quantile -> near-conflict-free quarters.
//  Main kernel identical to the 66us R5 version (schedule baked into layout).

#define IN_F   8192
#define OUT_F  8192
#define KW     32
#define BATCH  1024
#define BT     8
#define THREADS 1024
#define O_SPLIT 8
#define O_PER_CTA (OUT_F / O_SPLIT)     // 1024 == THREADS
#define SMEM_BYTES (IN_F * BT * (int)sizeof(__half))   // 131072

__device__ unsigned int g_cwT[KW * OUT_F];   // [slot][o] packed (idx<<16)|half(w)

static __device__ __forceinline__ __half2 u32_as_h2(unsigned int u) {
    __half2 h; memcpy(&h, &u, sizeof(h)); return h;
}

// One warp per output o; lane = k. Ballot counting-sort by bank group
// (idx & 7), then place rank r at slot (r - 4*o) & 31 so that runtime
// step t reads rank (t + 4*o) & 31.
__global__ void psl_prep(const int* __restrict__ conn, const float* __restrict__ w)
{
    const int gtid = blockIdx.x * blockDim.x + threadIdx.x;
    const int o    = gtid >> 5;          // warp id == output index
    const int lane = gtid & 31;          // k index

    const int   c  = conn[(size_t)o * KW + lane];
    const float wv = w   [(size_t)o * KW + lane];
    const unsigned short hb = __half_as_ushort(__float2half_rn(wv));
    const unsigned int packed = ((unsigned int)c << 16) | (unsigned int)hb;

    const int g = c & 7;                 // bank-group of xs[c] (16B granule)

    // rank = #entries with smaller group + #ties in lower lanes
    unsigned int rank = 0, my_mask = 0;
    #pragma unroll
    for (int gg = 0; gg < 8; gg++) {
        unsigned int m = __ballot_sync(0xffffffffu, g == gg);
        if (gg < g)  rank += __popc(m);
        if (gg == g) my_mask = m;
    }
    rank += __popc(my_mask & ((1u << lane) - 1u));

    // slot t holds the element of rank (t + 4*o) & 31
    const int slot = (int)((rank - 4u * (unsigned int)o) & 31u);
    g_cwT[(size_t)slot * OUT_F + o] = packed;
}

__global__ __launch_bounds__(THREADS, 1)
void psl_main(const float* __restrict__ x, float* __restrict__ out)
{
    extern __shared__ uint4 xs[];   // xs[col] = 8 halves: rows b0..b0+7 of col

    const int tid = threadIdx.x;
    const int b0  = blockIdx.y * BT;

    // ---- Stage: 8 coalesced row-loads per column -> fp16 pack -> STS.128 ----
    const float* xb = x + (size_t)b0 * IN_F;

    #pragma unroll
    for (int c = tid; c < IN_F; c += THREADS) {
        float r0 = xb[c + 0 * (size_t)IN_F];
        float r1 = xb[c + 1 * (size_t)IN_F];
        float r2 = xb[c + 2 * (size_t)IN_F];
        float r3 = xb[c + 3 * (size_t)IN_F];
        float r4 = xb[c + 4 * (size_t)IN_F];
        float r5 = xb[c + 5 * (size_t)IN_F];
        float r6 = xb[c + 6 * (size_t)IN_F];
        float r7 = xb[c + 7 * (size_t)IN_F];

        __half2 h0 = __floats2half2_rn(r0, r1);
        __half2 h1 = __floats2half2_rn(r2, r3);
        __half2 h2 = __floats2half2_rn(r4, r5);
        __half2 h3 = __floats2half2_rn(r6, r7);

        uint4 v;
        memcpy(&v.x, &h0, 4);
        memcpy(&v.y, &h1, 4);
        memcpy(&v.z, &h2, 4);
        memcpy(&v.w, &h3, 4);
        xs[c] = v;
    }
    __syncthreads();

    const int o = blockIdx.x * O_PER_CTA + tid;   // one output per thread
    const unsigned int* __restrict__ cwp = g_cwT + o;

    float a0 = 0.f, a1 = 0.f, a2 = 0.f, a3 = 0.f;
    float a4 = 0.f, a5 = 0.f, a6 = 0.f, a7 = 0.f;

    #pragma unroll 8
    for (int k = 0; k < KW; k++) {
        const unsigned int cw = cwp[(size_t)k * OUT_F];  // coalesced, L2-hot
        const int   c  = (int)(cw >> 16);
        const float wv = __half2float(__ushort_as_half((unsigned short)(cw & 0xffffu)));

        const uint4 hv = xs[c];
        float2 f0 = __half22float2(u32_as_h2(hv.x));
        float2 f1 = __half22float2(u32_as_h2(hv.y));
        float2 f2 = __half22float2(u32_as_h2(hv.z));
        float2 f3 = __half22float2(u32_as_h2(hv.w));
        a0 = fmaf(wv, f0.x, a0);
        a1 = fmaf(wv, f0.y, a1);
        a2 = fmaf(wv, f1.x, a2);
        a3 = fmaf(wv, f1.y, a3);
        a4 = fmaf(wv, f2.x, a4);
        a5 = fmaf(wv, f2.y, a5);
        a6 = fmaf(wv, f3.x, a6);
        a7 = fmaf(wv, f3.y, a7);
    }

    float* op = out + (size_t)b0 * OUT_F + o;
    op[0 * (size_t)OUT_F] = a0;
    op[1 * (size_t)OUT_F] = a1;
    op[2 * (size_t)OUT_F] = a2;
    op[3 * (size_t)OUT_F] = a3;
    op[4 * (size_t)OUT_F] = a4;
    op[5 * (size_t)OUT_F] = a5;
    op[6 * (size_t)OUT_F] = a6;
    op[7 * (size_t)OUT_F] = a7;
}

extern "C" void kernel_launch(void* const* d_in, const int* in_sizes, int n_in,
                              void* d_out, int out_size)
{
    const float* x    = (const float*)d_in[0];   // [1024, 8192] f32
    const int*   conn = (const int*)  d_in[1];   // [8192, 32]   i32
    const float* w    = (const float*)d_in[2];   // [8192, 32]   f32
    float*       out  = (float*)d_out;           // [1024, 8192] f32

    (void)in_sizes; (void)n_in; (void)out_size;

    psl_prep<<<(OUT_F * 32) / 256, 256>>>(conn, w);

    cudaFuncSetAttribute(psl_main,
                         cudaFuncAttributeMaxDynamicSharedMemorySize,
                         SMEM_BYTES);

    dim3 grid(O_SPLIT, BATCH / BT);   // (8, 128) = 1024 CTAs
    psl_main<<<grid, THREADS, SMEM_BYTES>>>(x, out);
}

// round 9
// speedup vs baseline: 1.7021x; 1.2070x over previous
#include <cuda_runtime.h>
#include <cuda_fp16.h>
#include <cstring>

// PositionalSparseLinear: out[b,o] = sum_k x[b, conn[o,k]] * w[o,k]
//   x: [1024,8192] f32   conn: [8192,32] i32   w: [8192,32] f32   out: [1024,8192] f32
//
// Round 9: one CTA per batch-tile (grid=128), each stages x ONCE into SMEM
// and loops over all 8192 outputs (8 chunks of 1024 threads). Removes the
// 8x staging redundancy of the O_SPLIT=8 layout (3.1M -> 0.39M L1tex
// wavefronts) at the cost of 20 idle SMs (128 CTAs / 148 SMs, single wave).
// Keeps: fp16-staged transposed tile (8 rows per 16B column) + stride-4
// bank-group-sorted metadata schedule from R8.

#define IN_F   8192
#define OUT_F  8192
#define KW     32
#define BATCH  1024
#define BT     8
#define THREADS 1024
#define N_CHUNK (OUT_F / THREADS)       // 8 output chunks per CTA
#define SMEM_BYTES (IN_F * BT * (int)sizeof(__half))   // 131072

__device__ unsigned int g_cwT[KW * OUT_F];   // [slot][o] packed (idx<<16)|half(w)

static __device__ __forceinline__ __half2 u32_as_h2(unsigned int u) {
    __half2 h; memcpy(&h, &u, sizeof(h)); return h;
}

// One warp per output o; lane = k. Ballot counting-sort by bank group
// (idx & 7), then place rank r at slot (r - 4*o) & 31 so that runtime
// step t reads rank (t + 4*o) & 31 (stride-4 within each 8-lane quarter
// -> near-conflict-free crossbar phases).
__global__ void psl_prep(const int* __restrict__ conn, const float* __restrict__ w)
{
    const int gtid = blockIdx.x * blockDim.x + threadIdx.x;
    const int o    = gtid >> 5;          // warp id == output index
    const int lane = gtid & 31;          // k index

    const int   c  = conn[(size_t)o * KW + lane];
    const float wv = w   [(size_t)o * KW + lane];
    const unsigned short hb = __half_as_ushort(__float2half_rn(wv));
    const unsigned int packed = ((unsigned int)c << 16) | (unsigned int)hb;

    const int g = c & 7;                 // bank-group of xs[c] (16B granule)

    unsigned int rank = 0, my_mask = 0;
    #pragma unroll
    for (int gg = 0; gg < 8; gg++) {
        unsigned int m = __ballot_sync(0xffffffffu, g == gg);
        if (gg < g)  rank += __popc(m);
        if (gg == g) my_mask = m;
    }
    rank += __popc(my_mask & ((1u << lane) - 1u));

    const int slot = (int)((rank - 4u * (unsigned int)o) & 31u);
    g_cwT[(size_t)slot * OUT_F + o] = packed;
}

__global__ __launch_bounds__(THREADS, 1)
void psl_main(const float* __restrict__ x, float* __restrict__ out)
{
    extern __shared__ uint4 xs[];   // xs[col] = 8 halves: rows b0..b0+7 of col

    const int tid = threadIdx.x;
    const int b0  = blockIdx.x * BT;

    // ---- Stage x tile ONCE: 8 coalesced row-loads per column -> STS.128 ----
    const float* xb = x + (size_t)b0 * IN_F;

    #pragma unroll
    for (int c = tid; c < IN_F; c += THREADS) {
        float r0 = xb[c + 0 * (size_t)IN_F];
        float r1 = xb[c + 1 * (size_t)IN_F];
        float r2 = xb[c + 2 * (size_t)IN_F];
        float r3 = xb[c + 3 * (size_t)IN_F];
        float r4 = xb[c + 4 * (size_t)IN_F];
        float r5 = xb[c + 5 * (size_t)IN_F];
        float r6 = xb[c + 6 * (size_t)IN_F];
        float r7 = xb[c + 7 * (size_t)IN_F];

        __half2 h0 = __floats2half2_rn(r0, r1);
        __half2 h1 = __floats2half2_rn(r2, r3);
        __half2 h2 = __floats2half2_rn(r4, r5);
        __half2 h3 = __floats2half2_rn(r6, r7);

        uint4 v;
        memcpy(&v.x, &h0, 4);
        memcpy(&v.y, &h1, 4);
        memcpy(&v.z, &h2, 4);
        memcpy(&v.w, &h3, 4);
        xs[c] = v;
    }
    __syncthreads();

    // ---- Loop over all outputs: 8 chunks of 1024 (one output per thread) ----
    #pragma unroll 1
    for (int chunk = 0; chunk < N_CHUNK; chunk++) {
        const int o = chunk * THREADS + tid;
        const unsigned int* __restrict__ cwp = g_cwT + o;

        float a0 = 0.f, a1 = 0.f, a2 = 0.f, a3 = 0.f;
        float a4 = 0.f, a5 = 0.f, a6 = 0.f, a7 = 0.f;

        #pragma unroll 8
        for (int k = 0; k < KW; k++) {
            const unsigned int cw = cwp[(size_t)k * OUT_F];  // coalesced, L2-hot
            const int   c  = (int)(cw >> 16);
            const float wv = __half2float(__ushort_as_half((unsigned short)(cw & 0xffffu)));

            const uint4 hv = xs[c];
            float2 f0 = __half22float2(u32_as_h2(hv.x));
            float2 f1 = __half22float2(u32_as_h2(hv.y));
            float2 f2 = __half22float2(u32_as_h2(hv.z));
            float2 f3 = __half22float2(u32_as_h2(hv.w));
            a0 = fmaf(wv, f0.x, a0);
            a1 = fmaf(wv, f0.y, a1);
            a2 = fmaf(wv, f1.x, a2);
            a3 = fmaf(wv, f1.y, a3);
            a4 = fmaf(wv, f2.x, a4);
            a5 = fmaf(wv, f2.y, a5);
            a6 = fmaf(wv, f3.x, a6);
            a7 = fmaf(wv, f3.y, a7);
        }

        float* op = out + (size_t)b0 * OUT_F + o;
        op[0 * (size_t)OUT_F] = a0;
        op[1 * (size_t)OUT_F] = a1;
        op[2 * (size_t)OUT_F] = a2;
        op[3 * (size_t)OUT_F] = a3;
        op[4 * (size_t)OUT_F] = a4;
        op[5 * (size_t)OUT_F] = a5;
        op[6 * (size_t)OUT_F] = a6;
        op[7 * (size_t)OUT_F] = a7;
    }
}

extern "C" void kernel_launch(void* const* d_in, const int* in_sizes, int n_in,
                              void* d_out, int out_size)
{
    const float* x    = (const float*)d_in[0];   // [1024, 8192] f32
    const int*   conn = (const int*)  d_in[1];   // [8192, 32]   i32
    const float* w    = (const float*)d_in[2];   // [8192, 32]   f32
    float*       out  = (float*)d_out;           // [1024, 8192] f32

    (void)in_sizes; (void)n_in; (void)out_size;

    psl_prep<<<(OUT_F * 32) / 256, 256>>>(conn, w);

    cudaFuncSetAttribute(psl_main,
                         cudaFuncAttributeMaxDynamicSharedMemorySize,
                         SMEM_BYTES);

    psl_main<<<BATCH / BT, THREADS, SMEM_BYTES>>>(x, out);   // 128 CTAs
}

// round 10
// speedup vs baseline: 1.7518x; 1.0292x over previous
#include <cuda_runtime.h>
#include <cuda_fp16.h>
#include <cstring>

// PositionalSparseLinear: out[b,o] = sum_k x[b, conn[o,k]] * w[o,k]
//   x: [1024,8192] f32   conn: [8192,32] i32   w: [8192,32] f32   out: [1024,8192] f32
//
// Round 10:
//  - fp16-staged transposed SMEM batch tile (BT=8 per 16B col) [R4]
//  - stride-4 bank-group-sorted metadata schedule [R8]
//  - NEW: packed f32x2 accumulation via PTX fma.rn.f32x2 (FFMA2): 8 FFMA ->
//    4 FFMA2 per k, halving fma-pipe pressure; numerically identical.
//  - NEW: flat (b-tile, o-chunk) work split over 148 CTAs (was 128): all
//    SMs active, single wave; CTAs crossing a b-tile boundary re-stage
//    (staging ~3K wf vs ~7.2K wf per chunk, so the trade wins).

#define IN_F   8192
#define OUT_F  8192
#define KW     32
#define BATCH  1024
#define BT     8
#define THREADS 1024
#define N_CTAS 148
#define CHUNKS_PER_BT (OUT_F / THREADS)            // 8
#define TOTAL_CHUNKS ((BATCH / BT) * CHUNKS_PER_BT) // 1024
#define SMEM_BYTES (IN_F * BT * (int)sizeof(__half))   // 131072

__device__ unsigned int g_cwT[KW * OUT_F];   // [slot][o] packed (idx<<16)|half(w)

static __device__ __forceinline__ __half2 u32_as_h2(unsigned int u) {
    __half2 h; memcpy(&h, &u, sizeof(h)); return h;
}

// One warp per output o; lane = k. Ballot counting-sort by bank group
// (idx & 7); slot t holds rank (t + 4*o) & 31 -> stride-4 ranks within
// each 8-lane quarter at runtime = near-conflict-free crossbar phases.
__global__ void psl_prep(const int* __restrict__ conn, const float* __restrict__ w)
{
    const int gtid = blockIdx.x * blockDim.x + threadIdx.x;
    const int o    = gtid >> 5;
    const int lane = gtid & 31;

    const int   c  = conn[(size_t)o * KW + lane];
    const float wv = w   [(size_t)o * KW + lane];
    const unsigned short hb = __half_as_ushort(__float2half_rn(wv));
    const unsigned int packed = ((unsigned int)c << 16) | (unsigned int)hb;

    const int g = c & 7;

    unsigned int rank = 0, my_mask = 0;
    #pragma unroll
    for (int gg = 0; gg < 8; gg++) {
        unsigned int m = __ballot_sync(0xffffffffu, g == gg);
        if (gg < g)  rank += __popc(m);
        if (gg == g) my_mask = m;
    }
    rank += __popc(my_mask & ((1u << lane) - 1u));

    const int slot = (int)((rank - 4u * (unsigned int)o) & 31u);
    g_cwT[(size_t)slot * OUT_F + o] = packed;
}

__global__ __launch_bounds__(THREADS, 1)
void psl_main(const float* __restrict__ x, float* __restrict__ out)
{
    extern __shared__ uint4 xs[];   // xs[col] = 8 halves: rows b0..b0+7 of col

    const int tid = threadIdx.x;
    const int bid = blockIdx.x;

    const int c_start = (bid * TOTAL_CHUNKS) / N_CTAS;
    const int c_end   = ((bid + 1) * TOTAL_CHUNKS) / N_CTAS;

    int cur_bt = -1;

    #pragma unroll 1
    for (int ch = c_start; ch < c_end; ch++) {
        const int bt = ch >> 3;            // b-tile index
        const int oc = ch & 7;             // output chunk within tile

        if (bt != cur_bt) {
            if (cur_bt >= 0) __syncthreads();   // drain readers of old tile
            const float* xb = x + (size_t)bt * BT * IN_F;
            #pragma unroll
            for (int c = tid; c < IN_F; c += THREADS) {
                float r0 = xb[c + 0 * (size_t)IN_F];
                float r1 = xb[c + 1 * (size_t)IN_F];
                float r2 = xb[c + 2 * (size_t)IN_F];
                float r3 = xb[c + 3 * (size_t)IN_F];
                float r4 = xb[c + 4 * (size_t)IN_F];
                float r5 = xb[c + 5 * (size_t)IN_F];
                float r6 = xb[c + 6 * (size_t)IN_F];
                float r7 = xb[c + 7 * (size_t)IN_F];

                __half2 h0 = __floats2half2_rn(r0, r1);
                __half2 h1 = __floats2half2_rn(r2, r3);
                __half2 h2 = __floats2half2_rn(r4, r5);
                __half2 h3 = __floats2half2_rn(r6, r7);

                uint4 v;
                memcpy(&v.x, &h0, 4);
                memcpy(&v.y, &h1, 4);
                memcpy(&v.z, &h2, 4);
                memcpy(&v.w, &h3, 4);
                xs[c] = v;
            }
            cur_bt = bt;
            __syncthreads();
        }

        const int o = oc * THREADS + tid;         // o % 32 == lane: sort holds
        const unsigned int* __restrict__ cwp = g_cwT + o;

        unsigned long long A01 = 0ull, A23 = 0ull, A45 = 0ull, A67 = 0ull;

        #pragma unroll 8
        for (int k = 0; k < KW; k++) {
            const unsigned int cw = cwp[(size_t)k * OUT_F];  // coalesced, L2-hot
            const int   c  = (int)(cw >> 16);
            const float wvf = __half2float(__ushort_as_half((unsigned short)(cw & 0xffffu)));
            unsigned long long WV2;
            asm("mov.b64 %0, {%1, %1};" : "=l"(WV2) : "f"(wvf));

            const uint4 hv = xs[c];
            float2 f0 = __half22float2(u32_as_h2(hv.x));
            float2 f1 = __half22float2(u32_as_h2(hv.y));
            float2 f2 = __half22float2(u32_as_h2(hv.z));
            float2 f3 = __half22float2(u32_as_h2(hv.w));

            unsigned long long F0, F1, F2, F3;
            asm("mov.b64 %0, {%1, %2};" : "=l"(F0) : "f"(f0.x), "f"(f0.y));
            asm("mov.b64 %0, {%1, %2};" : "=l"(F1) : "f"(f1.x), "f"(f1.y));
            asm("mov.b64 %0, {%1, %2};" : "=l"(F2) : "f"(f2.x), "f"(f2.y));
            asm("mov.b64 %0, {%1, %2};" : "=l"(F3) : "f"(f3.x), "f"(f3.y));

            asm("fma.rn.f32x2 %0, %1, %2, %0;" : "+l"(A01) : "l"(F0), "l"(WV2));
            asm("fma.rn.f32x2 %0, %1, %2, %0;" : "+l"(A23) : "l"(F1), "l"(WV2));
            asm("fma.rn.f32x2 %0, %1, %2, %0;" : "+l"(A45) : "l"(F2), "l"(WV2));
            asm("fma.rn.f32x2 %0, %1, %2, %0;" : "+l"(A67) : "l"(F3), "l"(WV2));
        }

        float a0, a1, a2, a3, a4, a5, a6, a7;
        asm("mov.b64 {%0, %1}, %2;" : "=f"(a0), "=f"(a1) : "l"(A01));
        asm("mov.b64 {%0, %1}, %2;" : "=f"(a2), "=f"(a3) : "l"(A23));
        asm("mov.b64 {%0, %1}, %2;" : "=f"(a4), "=f"(a5) : "l"(A45));
        asm("mov.b64 {%0, %1}, %2;" : "=f"(a6), "=f"(a7) : "l"(A67));

        float* op = out + (size_t)bt * BT * OUT_F + o;
        op[0 * (size_t)OUT_F] = a0;
        op[1 * (size_t)OUT_F] = a1;
        op[2 * (size_t)OUT_F] = a2;
        op[3 * (size_t)OUT_F] = a3;
        op[4 * (size_t)OUT_F] = a4;
        op[5 * (size_t)OUT_F] = a5;
        op[6 * (size_t)OUT_F] = a6;
        op[7 * (size_t)OUT_F] = a7;
    }
}

extern "C" void kernel_launch(void* const* d_in, const int* in_sizes, int n_in,
                              void* d_out, int out_size)
{
    const float* x    = (const float*)d_in[0];   // [1024, 8192] f32
    const int*   conn = (const int*)  d_in[1];   // [8192, 32]   i32
    const float* w    = (const float*)d_in[2];   // [8192, 32]   f32
    float*       out  = (float*)d_out;           // [1024, 8192] f32

    (void)in_sizes; (void)n_in; (void)out_size;

    psl_prep<<<(OUT_F * 32) / 256, 256>>>(conn, w);

    cudaFuncSetAttribute(psl_main,
                         cudaFuncAttributeMaxDynamicSharedMemorySize,
                         SMEM_BYTES);

    psl_main<<<N_CTAS, THREADS, SMEM_BYTES>>>(x, out);   // 148 CTAs, 1 wave
}

// round 11
// speedup vs baseline: 1.9599x; 1.1188x over previous
#include <cuda_runtime.h>
#include <cuda_fp16.h>
#include <cstring>

// PositionalSparseLinear: out[b,o] = sum_k x[b, conn[o,k]] * w[o,k]
//   x: [1024,8192] f32   conn: [8192,32] i32   w: [8192,32] f32   out: [1024,8192] f32
//
// Round 11:
//  - fp16-staged transposed SMEM batch tile (BT=8 per 16B col) [R4]
//  - flat (b-tile, o-chunk) split over 148 CTAs, FFMA2 accumulation [R10]
//  - NEW: histogram-aware bank schedule. Slot t of output o targets bank
//    group (t/4 + o) & 7 -> the 8 lanes of every warp-quarter hit 8
//    DISTINCT groups wherever targets are met. Entries with within-group
//    rank < 4 claim their group's 4 slots; surplus entries fill deficit
//    slots. ~26/32 slots conflict-free vs rank-stride-4's boundary
//    collisions: expected phases/LDS.128 ~4.8 (floor 4, was ~5.7).

#define IN_F   8192
#define OUT_F  8192
#define KW     32
#define BATCH  1024
#define BT     8
#define THREADS 1024
#define N_CTAS 148
#define CHUNKS_PER_BT (OUT_F / THREADS)             // 8
#define TOTAL_CHUNKS ((BATCH / BT) * CHUNKS_PER_BT) // 1024
#define SMEM_BYTES (IN_F * BT * (int)sizeof(__half))   // 131072

__device__ unsigned int g_cwT[KW * OUT_F];   // [slot][o] packed (idx<<16)|half(w)

static __device__ __forceinline__ __half2 u32_as_h2(unsigned int u) {
    __half2 h; memcpy(&h, &u, sizeof(h)); return h;
}

// One warp per output o; lane = k.
// Slot block for group g of output o: slots [4*((g-o)&7), +4).
// Entry of group g with within-group rank r<4 -> slot 4*((g-o)&7)+r.
// Surplus entries (r>=4) fill deficit slots (groups with h<4) by ordered match.
__global__ void psl_prep(const int* __restrict__ conn, const float* __restrict__ w)
{
    const int gtid = blockIdx.x * blockDim.x + threadIdx.x;
    const int o    = gtid >> 5;
    const int lane = gtid & 31;

    const int   c  = conn[(size_t)o * KW + lane];
    const float wv = w   [(size_t)o * KW + lane];
    const unsigned short hb = __half_as_ushort(__float2half_rn(wv));
    const unsigned int packed = ((unsigned int)c << 16) | (unsigned int)hb;

    const int g = c & 7;
    const unsigned int lt = (1u << lane) - 1u;

    int cnt[8];
    int r = 0;
    #pragma unroll
    for (int gg = 0; gg < 8; gg++) {
        unsigned int m = __ballot_sync(0xffffffffu, g == gg);
        cnt[gg] = __popc(m);
        if (gg == g) r = __popc(m & lt);
    }

    int slot;
    if (r < 4) {
        slot = 4 * ((g - o) & 7) + r;
    } else {
        // leftover index among surplus entries (lane-ordered)
        unsigned int lm = __ballot_sync(0xffffffffu, r >= 4);
        // NOTE: all lanes execute the ballot above via the uniform path:
        // predicate differs per lane, mask full — fine.
        int i = __popc(lm & lt);
        int cum = 0, slotg = 0, j = 0;
        #pragma unroll
        for (int gg = 0; gg < 8; gg++) {
            int def = cnt[gg] < 4 ? 4 - cnt[gg] : 0;
            if (i >= cum && i < cum + def) { slotg = gg; j = cnt[gg] + (i - cum); }
            cum += def;
        }
        slot = 4 * ((slotg - o) & 7) + j;
    }

    g_cwT[(size_t)slot * OUT_F + o] = packed;
}

__global__ __launch_bounds__(THREADS, 1)
void psl_main(const float* __restrict__ x, float* __restrict__ out)
{
    extern __shared__ uint4 xs[];   // xs[col] = 8 halves: rows b0..b0+7 of col

    const int tid = threadIdx.x;
    const int bid = blockIdx.x;

    const int c_start = (bid * TOTAL_CHUNKS) / N_CTAS;
    const int c_end   = ((bid + 1) * TOTAL_CHUNKS) / N_CTAS;

    int cur_bt = -1;

    #pragma unroll 1
    for (int ch = c_start; ch < c_end; ch++) {
        const int bt = ch >> 3;            // b-tile index
        const int oc = ch & 7;             // output chunk within tile

        if (bt != cur_bt) {
            if (cur_bt >= 0) __syncthreads();   // drain readers of old tile
            const float* xb = x + (size_t)bt * BT * IN_F;
            #pragma unroll
            for (int c = tid; c < IN_F; c += THREADS) {
                float r0 = xb[c + 0 * (size_t)IN_F];
                float r1 = xb[c + 1 * (size_t)IN_F];
                float r2 = xb[c + 2 * (size_t)IN_F];
                float r3 = xb[c + 3 * (size_t)IN_F];
                float r4 = xb[c + 4 * (size_t)IN_F];
                float r5 = xb[c + 5 * (size_t)IN_F];
                float r6 = xb[c + 6 * (size_t)IN_F];
                float r7 = xb[c + 7 * (size_t)IN_F];

                __half2 h0 = __floats2half2_rn(r0, r1);
                __half2 h1 = __floats2half2_rn(r2, r3);
                __half2 h2 = __floats2half2_rn(r4, r5);
                __half2 h3 = __floats2half2_rn(r6, r7);

                uint4 v;
                memcpy(&v.x, &h0, 4);
                memcpy(&v.y, &h1, 4);
                memcpy(&v.z, &h2, 4);
                memcpy(&v.w, &h3, 4);
                xs[c] = v;
            }
            cur_bt = bt;
            __syncthreads();
        }

        const int o = oc * THREADS + tid;         // o % 32 == lane: schedule holds
        const unsigned int* __restrict__ cwp = g_cwT + o;

        unsigned long long A01 = 0ull, A23 = 0ull, A45 = 0ull, A67 = 0ull;

        #pragma unroll 8
        for (int k = 0; k < KW; k++) {
            const unsigned int cw = cwp[(size_t)k * OUT_F];  // coalesced, L2-hot
            const int   c  = (int)(cw >> 16);
            const float wvf = __half2float(__ushort_as_half((unsigned short)(cw & 0xffffu)));
            unsigned long long WV2;
            asm("mov.b64 %0, {%1, %1};" : "=l"(WV2) : "f"(wvf));

            const uint4 hv = xs[c];
            float2 f0 = __half22float2(u32_as_h2(hv.x));
            float2 f1 = __half22float2(u32_as_h2(hv.y));
            float2 f2 = __half22float2(u32_as_h2(hv.z));
            float2 f3 = __half22float2(u32_as_h2(hv.w));

            unsigned long long F0, F1, F2, F3;
            asm("mov.b64 %0, {%1, %2};" : "=l"(F0) : "f"(f0.x), "f"(f0.y));
            asm("mov.b64 %0, {%1, %2};" : "=l"(F1) : "f"(f1.x), "f"(f1.y));
            asm("mov.b64 %0, {%1, %2};" : "=l"(F2) : "f"(f2.x), "f"(f2.y));
            asm("mov.b64 %0, {%1, %2};" : "=l"(F3) : "f"(f3.x), "f"(f3.y));

            asm("fma.rn.f32x2 %0, %1, %2, %0;" : "+l"(A01) : "l"(F0), "l"(WV2));
            asm("fma.rn.f32x2 %0, %1, %2, %0;" : "+l"(A23) : "l"(F1), "l"(WV2));
            asm("fma.rn.f32x2 %0, %1, %2, %0;" : "+l"(A45) : "l"(F2), "l"(WV2));
            asm("fma.rn.f32x2 %0, %1, %2, %0;" : "+l"(A67) : "l"(F3), "l"(WV2));
        }

        float a0, a1, a2, a3, a4, a5, a6, a7;
        asm("mov.b64 {%0, %1}, %2;" : "=f"(a0), "=f"(a1) : "l"(A01));
        asm("mov.b64 {%0, %1}, %2;" : "=f"(a2), "=f"(a3) : "l"(A23));
        asm("mov.b64 {%0, %1}, %2;" : "=f"(a4), "=f"(a5) : "l"(A45));
        asm("mov.b64 {%0, %1}, %2;" : "=f"(a6), "=f"(a7) : "l"(A67));

        float* op = out + (size_t)bt * BT * OUT_F + o;
        op[0 * (size_t)OUT_F] = a0;
        op[1 * (size_t)OUT_F] = a1;
        op[2 * (size_t)OUT_F] = a2;
        op[3 * (size_t)OUT_F] = a3;
        op[4 * (size_t)OUT_F] = a4;
        op[5 * (size_t)OUT_F] = a5;
        op[6 * (size_t)OUT_F] = a6;
        op[7 * (size_t)OUT_F] = a7;
    }
}

extern "C" void kernel_launch(void* const* d_in, const int* in_sizes, int n_in,
                              void* d_out, int out_size)
{
    const float* x    = (const float*)d_in[0];   // [1024, 8192] f32
    const int*   conn = (const int*)  d_in[1];   // [8192, 32]   i32
    const float* w    = (const float*)d_in[2];   // [8192, 32]   f32
    float*       out  = (float*)d_out;           // [1024, 8192] f32

    (void)in_sizes; (void)n_in; (void)out_size;

    psl_prep<<<(OUT_F * 32) / 256, 256>>>(conn, w);

    cudaFuncSetAttribute(psl_main,
                         cudaFuncAttributeMaxDynamicSharedMemorySize,
                         SMEM_BYTES);

    psl_main<<<N_CTAS, THREADS, SMEM_BYTES>>>(x, out);   // 148 CTAs, 1 wave
}

// round 12
// speedup vs baseline: 1.9628x; 1.0015x over previous
#include <cuda_runtime.h>
#include <cuda_fp16.h>
#include <cstring>

// PositionalSparseLinear: out[b,o] = sum_k x[b, conn[o,k]] * w[o,k]
//   x: [1024,8192] f32   conn: [8192,32] i32   w: [8192,32] f32   out: [1024,8192] f32
//
// Round 12:
//  - fp16-staged transposed SMEM batch tile (BT=8 per 16B col) [R4]
//  - histogram-aware bank-group schedule (slot t targets group (t/4+o)&7) [R11]
//  - flat (b-tile, o-chunk) split over 148 CTAs, FFMA2 accumulation [R10]
//  - NEW: 512 threads, TWO outputs per thread (o, o+512). Doubles the
//    register budget (64 -> 128) and gives each warp two independent
//    LDG->LDS->FFMA2 chains: same L1 wavefront totals, better latency
//    coverage (L1 util 72% -> target ~80%).

#define IN_F   8192
#define OUT_F  8192
#define KW     32
#define BATCH  1024
#define BT     8
#define THREADS 512
#define N_CTAS 148
#define CHUNKS_PER_BT 8                               // 1024 outputs per chunk
#define TOTAL_CHUNKS ((BATCH / BT) * CHUNKS_PER_BT)   // 1024
#define SMEM_BYTES (IN_F * BT * (int)sizeof(__half))  // 131072

__device__ unsigned int g_cwT[KW * OUT_F];   // [slot][o] packed (idx<<16)|half(w)

static __device__ __forceinline__ __half2 u32_as_h2(unsigned int u) {
    __half2 h; memcpy(&h, &u, sizeof(h)); return h;
}

// One warp per output o; lane = k.
// Slot block for group g of output o: slots [4*((g-o)&7), +4).
// Entry of group g with within-group rank r<4 -> slot 4*((g-o)&7)+r.
// Surplus entries (r>=4) fill deficit slots (groups with h<4) by ordered match.
__global__ void psl_prep(const int* __restrict__ conn, const float* __restrict__ w)
{
    const int gtid = blockIdx.x * blockDim.x + threadIdx.x;
    const int o    = gtid >> 5;
    const int lane = gtid & 31;

    const int   c  = conn[(size_t)o * KW + lane];
    const float wv = w   [(size_t)o * KW + lane];
    const unsigned short hb = __half_as_ushort(__float2half_rn(wv));
    const unsigned int packed = ((unsigned int)c << 16) | (unsigned int)hb;

    const int g = c & 7;
    const unsigned int lt = (1u << lane) - 1u;

    int cnt[8];
    int r = 0;
    #pragma unroll
    for (int gg = 0; gg < 8; gg++) {
        unsigned int m = __ballot_sync(0xffffffffu, g == gg);
        cnt[gg] = __popc(m);
        if (gg == g) r = __popc(m & lt);
    }

    int slot;
    unsigned int lm = __ballot_sync(0xffffffffu, r >= 4);
    if (r < 4) {
        slot = 4 * ((g - o) & 7) + r;
    } else {
        int i = __popc(lm & lt);
        int cum = 0, slotg = 0, j = 0;
        #pragma unroll
        for (int gg = 0; gg < 8; gg++) {
            int def = cnt[gg] < 4 ? 4 - cnt[gg] : 0;
            if (i >= cum && i < cum + def) { slotg = gg; j = cnt[gg] + (i - cum); }
            cum += def;
        }
        slot = 4 * ((slotg - o) & 7) + j;
    }

    g_cwT[(size_t)slot * OUT_F + o] = packed;
}

__global__ __launch_bounds__(THREADS, 1)
void psl_main(const float* __restrict__ x, float* __restrict__ out)
{
    extern __shared__ uint4 xs[];   // xs[col] = 8 halves: rows b0..b0+7 of col

    const int tid = threadIdx.x;
    const int bid = blockIdx.x;

    const int c_start = (bid * TOTAL_CHUNKS) / N_CTAS;
    const int c_end   = ((bid + 1) * TOTAL_CHUNKS) / N_CTAS;

    int cur_bt = -1;

    #pragma unroll 1
    for (int ch = c_start; ch < c_end; ch++) {
        const int bt = ch >> 3;            // b-tile index
        const int oc = ch & 7;             // output chunk within tile

        if (bt != cur_bt) {
            if (cur_bt >= 0) __syncthreads();   // drain readers of old tile
            const float* xb = x + (size_t)bt * BT * IN_F;
            #pragma unroll
            for (int c = tid; c < IN_F; c += THREADS) {
                float r0 = xb[c + 0 * (size_t)IN_F];
                float r1 = xb[c + 1 * (size_t)IN_F];
                float r2 = xb[c + 2 * (size_t)IN_F];
                float r3 = xb[c + 3 * (size_t)IN_F];
                float r4 = xb[c + 4 * (size_t)IN_F];
                float r5 = xb[c + 5 * (size_t)IN_F];
                float r6 = xb[c + 6 * (size_t)IN_F];
                float r7 = xb[c + 7 * (size_t)IN_F];

                __half2 h0 = __floats2half2_rn(r0, r1);
                __half2 h1 = __floats2half2_rn(r2, r3);
                __half2 h2 = __floats2half2_rn(r4, r5);
                __half2 h3 = __floats2half2_rn(r6, r7);

                uint4 v;
                memcpy(&v.x, &h0, 4);
                memcpy(&v.y, &h1, 4);
                memcpy(&v.z, &h2, 4);
                memcpy(&v.w, &h3, 4);
                xs[c] = v;
            }
            cur_bt = bt;
            __syncthreads();
        }

        // Two outputs per thread: o1 and o1+512. Both preserve o%32==lane.
        const int o1 = oc * 1024 + tid;
        const unsigned int* __restrict__ cwp1 = g_cwT + o1;
        const unsigned int* __restrict__ cwp2 = g_cwT + o1 + 512;

        unsigned long long A01 = 0ull, A23 = 0ull, A45 = 0ull, A67 = 0ull;
        unsigned long long B01 = 0ull, B23 = 0ull, B45 = 0ull, B67 = 0ull;

        #pragma unroll 8
        for (int k = 0; k < KW; k++) {
            const unsigned int cw1 = cwp1[(size_t)k * OUT_F];
            const unsigned int cw2 = cwp2[(size_t)k * OUT_F];

            #define PSL_BODY(CW, P01, P23, P45, P67) {                          \
                const int   c_  = (int)((CW) >> 16);                             \
                const float wvf = __half2float(__ushort_as_half(                 \
                                      (unsigned short)((CW) & 0xffffu)));        \
                unsigned long long WV2;                                          \
                asm("mov.b64 %0, {%1, %1};" : "=l"(WV2) : "f"(wvf));             \
                const uint4 hv = xs[c_];                                         \
                float2 f0 = __half22float2(u32_as_h2(hv.x));                     \
                float2 f1 = __half22float2(u32_as_h2(hv.y));                     \
                float2 f2 = __half22float2(u32_as_h2(hv.z));                     \
                float2 f3 = __half22float2(u32_as_h2(hv.w));                     \
                unsigned long long F0, F1, F2, F3;                               \
                asm("mov.b64 %0, {%1, %2};" : "=l"(F0) : "f"(f0.x), "f"(f0.y));  \
                asm("mov.b64 %0, {%1, %2};" : "=l"(F1) : "f"(f1.x), "f"(f1.y));  \
                asm("mov.b64 %0, {%1, %2};" : "=l"(F2) : "f"(f2.x), "f"(f2.y));  \
                asm("mov.b64 %0, {%1, %2};" : "=l"(F3) : "f"(f3.x), "f"(f3.y));  \
                asm("fma.rn.f32x2 %0, %1, %2, %0;" : "+l"(P01) : "l"(F0), "l"(WV2)); \
                asm("fma.rn.f32x2 %0, %1, %2, %0;" : "+l"(P23) : "l"(F1), "l"(WV2)); \
                asm("fma.rn.f32x2 %0, %1, %2, %0;" : "+l"(P45) : "l"(F2), "l"(WV2)); \
                asm("fma.rn.f32x2 %0, %1, %2, %0;" : "+l"(P67) : "l"(F3), "l"(WV2)); \
            }
            PSL_BODY(cw1, A01, A23, A45, A67);
            PSL_BODY(cw2, B01, B23, B45, B67);
            #undef PSL_BODY
        }

        float a0, a1, a2, a3, a4, a5, a6, a7;
        float b0, b1, b2, b3, b4, b5, b6, b7;
        asm("mov.b64 {%0, %1}, %2;" : "=f"(a0), "=f"(a1) : "l"(A01));
        asm("mov.b64 {%0, %1}, %2;" : "=f"(a2), "=f"(a3) : "l"(A23));
        asm("mov.b64 {%0, %1}, %2;" : "=f"(a4), "=f"(a5) : "l"(A45));
        asm("mov.b64 {%0, %1}, %2;" : "=f"(a6), "=f"(a7) : "l"(A67));
        asm("mov.b64 {%0, %1}, %2;" : "=f"(b0), "=f"(b1) : "l"(B01));
        asm("mov.b64 {%0, %1}, %2;" : "=f"(b2), "=f"(b3) : "l"(B23));
        asm("mov.b64 {%0, %1}, %2;" : "=f"(b4), "=f"(b5) : "l"(B45));
        asm("mov.b64 {%0, %1}, %2;" : "=f"(b6), "=f"(b7) : "l"(B67));

        float* op1 = out + (size_t)bt * BT * OUT_F + o1;
        float* op2 = op1 + 512;
        op1[0 * (size_t)OUT_F] = a0;  op2[0 * (size_t)OUT_F] = b0;
        op1[1 * (size_t)OUT_F] = a1;  op2[1 * (size_t)OUT_F] = b1;
        op1[2 * (size_t)OUT_F] = a2;  op2[2 * (size_t)OUT_F] = b2;
        op1[3 * (size_t)OUT_F] = a3;  op2[3 * (size_t)OUT_F] = b3;
        op1[4 * (size_t)OUT_F] = a4;  op2[4 * (size_t)OUT_F] = b4;
        op1[5 * (size_t)OUT_F] = a5;  op2[5 * (size_t)OUT_F] = b5;
        op1[6 * (size_t)OUT_F] = a6;  op2[6 * (size_t)OUT_F] = b6;
        op1[7 * (size_t)OUT_F] = a7;  op2[7 * (size_t)OUT_F] = b7;
    }
}

extern "C" void kernel_launch(void* const* d_in, const int* in_sizes, int n_in,
                              void* d_out, int out_size)
{
    const float* x    = (const float*)d_in[0];   // [1024, 8192] f32
    const int*   conn = (const int*)  d_in[1];   // [8192, 32]   i32
    const float* w    = (const float*)d_in[2];   // [8192, 32]   f32
    float*       out  = (float*)d_out;           // [1024, 8192] f32

    (void)in_sizes; (void)n_in; (void)out_size;

    psl_prep<<<(OUT_F * 32) / 256, 256>>>(conn, w);

    cudaFuncSetAttribute(psl_main,
                         cudaFuncAttributeMaxDynamicSharedMemorySize,
                         SMEM_BYTES);

    psl_main<<<N_CTAS, THREADS, SMEM_BYTES>>>(x, out);   // 148 CTAs, 1 wave
}